// round 11
// baseline (speedup 1.0000x reference)
#include <cuda_runtime.h>

// QNN_72988674228630: 10-qubit, 2-layer RY+CNOT circuit, 8192 circuits.
// R11: ONE circuit per warp (8192 warps -> ~55 warps/SM grid ceiling) with the
// R10 fused tail (small live set). ILP-2 removed: it capped the grid at 27.7
// warps/SM, which was the real limiter (occ 34%, issue 61%).
//
// Index i (10 bits): lane = bits 9..5, reg j = bits 4..0.
// Chain P is GF(2)-linear: psi_f = P R P psi1 = P^2 (P^-1 R P) psi1.
// - chain2 folded into readout diagonal -> 12-entry coeff table.
// - chain1 conjugates layer-2 RYs onto masks e_k^e_{k-1}; applied to the
//   product state psi1 as a doubling cascade.
// - stages q=6..q=9 + readout fused into one loop over W2 pairs (group
//   closure: amps 8g..8g+7 depend only on W2[g], W2[g^1]); W3/W4 arrays never
//   materialize. Each cascade step = 1 FMUL + 1 FFMA via hoisted angle
//   products with compile-time sign folding.

#define FULL 0xffffffffu

__device__ constexpr int NEf(int j) {   // #even-position M^2 bits set, from j
    const int j4 = (j >> 4) & 1, j2 = (j >> 2) & 1, j0 = j & 1;
    return j4 + (j2 ^ j4) + (j0 ^ j2 ^ j4);
}
__device__ constexpr int NOf(int j) {   // #odd-position M^2 bits set, from j
    const int j3 = (j >> 3) & 1, j1 = (j >> 1) & 1;
    return j3 + (j1 ^ j3);
}
__device__ constexpr int PARf(int m) {
    return (m ^ (m >> 1) ^ (m >> 2) ^ (m >> 3) ^ (m >> 4)) & 1;
}

// Angle layout per circuit (40 floats): [q]=c1, [10+q]=s1, [20+q]=c2, [30+q]=s2.

__global__ __launch_bounds__(256)
void qnn_kernel(const float* __restrict__ x,      // [128, 10]
                const float* __restrict__ w,      // [64, 10, 2]
                float* __restrict__ out)          // [64, 128] flat
{
    __shared__ float angs[8][40];
    const int wib  = threadIdx.x >> 5;
    const int warp = blockIdx.x * 8 + wib;        // 0..8191, one circuit
    const int lane = threadIdx.x & 31;
    const int of = warp >> 7;
    const int nb = warp & 127;

    // --- Angles: lanes 0..9 -> sincos((x_q + w_q0)/2); lanes 10..19 -> w_q1/2.
    if (lane < 20) {
        const float t = (lane < 10)
            ? x[nb * 10 + lane] + w[of * 20 + lane * 2]
            : w[of * 20 + (lane - 10) * 2 + 1];
        float s, c; __sincosf(0.5f * t, &s, &c);
        const int base = (lane < 10) ? lane : (10 + lane);
        angs[wib][base] = c; angs[wib][base + 10] = s;
    }
    __syncwarp();
    const float* const A = angs[wib];

    // --- Lane-bit suffix parities.
    const int p4  = (lane >> 4) & 1;
    const int p3  = p4 ^ ((lane >> 3) & 1);
    const int p2  = p3 ^ ((lane >> 2) & 1);
    const int p1  = p2 ^ ((lane >> 1) & 1);
    const int par = p1 ^ (lane & 1);

    // --- Lane factor of the product state (lane bit b <-> qubit 4-b).
    float lf;
    {
        const float f0 = (lane & 1)        ? A[14] : A[4];
        const float f1 = ((lane >> 1) & 1) ? A[13] : A[3];
        const float f2 = ((lane >> 2) & 1) ? A[12] : A[2];
        const float f3 = ((lane >> 3) & 1) ? A[11] : A[1];
        const float f4 = ((lane >> 4) & 1) ? A[10] : A[0];
        lf = (f0 * f1) * (f2 * f3) * f4;
    }

    // --- Conjugated gates q=0..3 (lane-factor only). Masks 24,12,6,3.
    {
        float ss, p;
        ss = p4 ? A[30] : -A[30];
        p = __shfl_xor_sync(FULL, lf, 24); lf = fmaf(A[20], lf, ss * p);
        ss = p3 ? A[31] : -A[31];
        p = __shfl_xor_sync(FULL, lf, 12); lf = fmaf(A[21], lf, ss * p);
        ss = p2 ? A[32] : -A[32];
        p = __shfl_xor_sync(FULL, lf, 6);  lf = fmaf(A[22], lf, ss * p);
        ss = p1 ? A[33] : -A[33];
        p = __shfl_xor_sync(FULL, lf, 3);  lf = fmaf(A[23], lf, ss * p);
    }

    // --- q=4 boundary + q=5: materialize W2[4] with hoisted products.
    float W2[4];
    {
        const float Lp   = __shfl_xor_sync(FULL, lf, 1);
        const float sp4v = par ? A[34] : -A[34];
        const float q4cc = A[24] * A[5],  q4cs = A[24] * A[15];
        const float q4ss = sp4v  * A[15], q4sc = sp4v  * A[5];
        const float W1_0 = fmaf(q4cc, lf, q4ss * Lp);
        const float W1_1 = fmaf(q4cs, lf, q4sc * Lp);
        const float sp5v = par ? A[35] : -A[35];
        const float q5cc = A[25] * A[6],  q5cs = A[25] * A[16];
        const float q5ss = sp5v  * A[16], q5sc = sp5v  * A[6];
        W2[0] = fmaf(q5cc, W1_0,  q5ss * W1_1);
        W2[1] = fmaf(q5cs, W1_0,  q5sc * W1_1);
        W2[2] = fmaf(q5cc, W1_1, -q5ss * W1_0);
        W2[3] = fmaf(q5cs, W1_1, -q5sc * W1_0);
    }

    // --- Readout coefficient table: coeff = K + ke*ne + ko*no (12 values).
    const int E  = ((lane >> 1) ^ (lane >> 3)) & 1;
    const int O  = par ^ E;
    const int Ab = O + E + (((lane >> 2) ^ (lane >> 4)) & 1)
                 + ((lane >> 3) & 1) + ((lane >> 4) & 1);
    const float K  = (float)(10 - 2 * Ab - (E ? 6 : 0) - (O ? 4 : 0));
    const float ke = E ? 2.0f : -2.0f;
    const float ko = O ? 2.0f : -2.0f;
    float co[12];                         // co[ne*3 + no]
    co[0] = K;          co[3] = K + ke;     co[6] = co[3] + ke;  co[9]  = co[6] + ke;
    co[1] = co[0] + ko; co[4] = co[3] + ko; co[7] = co[6] + ko;  co[10] = co[9] + ko;
    co[2] = co[1] + ko; co[5] = co[4] + ko; co[8] = co[7] + ko;  co[11] = co[10] + ko;

    // --- Fused tail q=6..q=9 + readout.
    // q=6 products.
    const float sp6v = par ? A[36] : -A[36];
    const float q6cc = A[26] * A[7],  q6cs = A[26] * A[17];
    const float q6ss = sp6v  * A[17], q6sc = sp6v  * A[7];
    // q=7 products.
    const float sp7v = par ? A[37] : -A[37];
    const float q7cc = A[27] * A[8],  q7cs = A[27] * A[18];
    const float q7ss = sp7v  * A[18], q7sc = sp7v  * A[8];
    // Fused q=8+q=9 constants (e = parity of W4 index).
    float Ae[2], Be[2], Ce[2], De[2];
    {
        const float c9 = A[9], s9 = A[19], c29 = A[29], c28 = A[28];
        const float sp9v = par ? A[39] : -A[39];
        const float sp8v = par ? A[38] : -A[38];
        const float P = c29 * c9, Q = c29 * s9;
        const float R = sp9v * s9, Sg = sp9v * c9;
        const float Up = P + R, Um = P - R, Vp = Q + Sg, Vm = Q - Sg;
        Ae[0] = c28 * Up;  Be[0] = sp8v * Vp;   Ce[0] = c28 * Vm;  De[0] = sp8v * Um;
        Ae[1] = c28 * Um;  Be[1] = -sp8v * Vm;  Ce[1] = c28 * Vp;  De[1] = -sp8v * Up;
    }

    float s0 = 0.0f, s1 = 0.0f;
#pragma unroll
    for (int g = 0; g < 4; g++) {
        const int e0 = PARf(g), e1 = e0 ^ 1;    // compile-time
        const float u0 = W2[g], u1 = W2[g ^ 1];
        // q=6: W3 pair for this group.
        const float w30 = fmaf(q6cc, u0, (e0 ? -q6ss : q6ss) * u1);
        const float w31 = fmaf(q6cs, u0, (e0 ? -q6sc : q6sc) * u1);
        // q=7: W4 quad.
        const float w40 = fmaf(q7cc, w30, (e0 ? -q7ss : q7ss) * w31);
        const float w41 = fmaf(q7cs, w30, (e0 ? -q7sc : q7sc) * w31);
        const float w42 = fmaf(q7cc, w31, (e0 ? q7ss : -q7ss) * w30);
        const float w43 = fmaf(q7cs, w31, (e0 ? q7sc : -q7sc) * w30);
        // q=8+q=9 fused amps; square-accumulate with compile-time co indices.
        const float a0 = fmaf(Ae[e0], w40, Be[e0] * w41);
        const float a1 = fmaf(Ce[e0], w40, De[e0] * w41);
        const float a2 = fmaf(Ae[e1], w41, Be[e1] * w40);
        const float a3 = fmaf(Ce[e1], w41, De[e1] * w40);
        const float a4 = fmaf(Ae[e1], w42, Be[e1] * w43);
        const float a5 = fmaf(Ce[e1], w42, De[e1] * w43);
        const float a6 = fmaf(Ae[e0], w43, Be[e0] * w42);
        const float a7 = fmaf(Ce[e0], w43, De[e0] * w42);
        s0 = fmaf(a0 * a0, co[NEf(8*g+0)*3 + NOf(8*g+0)], s0);
        s1 = fmaf(a1 * a1, co[NEf(8*g+1)*3 + NOf(8*g+1)], s1);
        s0 = fmaf(a2 * a2, co[NEf(8*g+2)*3 + NOf(8*g+2)], s0);
        s1 = fmaf(a3 * a3, co[NEf(8*g+3)*3 + NOf(8*g+3)], s1);
        s0 = fmaf(a4 * a4, co[NEf(8*g+4)*3 + NOf(8*g+4)], s0);
        s1 = fmaf(a5 * a5, co[NEf(8*g+5)*3 + NOf(8*g+5)], s1);
        s0 = fmaf(a6 * a6, co[NEf(8*g+6)*3 + NOf(8*g+6)], s0);
        s1 = fmaf(a7 * a7, co[NEf(8*g+7)*3 + NOf(8*g+7)], s1);
    }
    float sum = s0 + s1;

    // --- Warp reduction.
#pragma unroll
    for (int off = 16; off; off >>= 1)
        sum += __shfl_xor_sync(FULL, sum, off);

    if (lane == 0) out[warp] = sum;
}

extern "C" void kernel_launch(void* const* d_in, const int* in_sizes, int n_in,
                              void* d_out, int out_size)
{
    const float* x = (const float*)d_in[0];   // (128, 10) fp32
    const float* w = (const float*)d_in[1];   // (64, 10, 2) fp32
    float* out = (float*)d_out;               // 8192 fp32

    // 8192 warps, 8 per block -> 1024 blocks of 256 threads.
    qnn_kernel<<<1024, 256>>>(x, w, out);
}

// round 12
// speedup vs baseline: 1.2977x; 1.2977x over previous
#include <cuda_runtime.h>

// QNN_72988674228630: 10-qubit, 2-layer RY+CNOT circuit, 8192 circuits.
//
// R12: COMPLEXITY-CLASS CHANGE. Instead of simulating the 1024-amp state
// vector (one warp/circuit, ~670 warp-issues each), evaluate the observable
// as a bond-dimension-2 MPS transfer-matrix contraction: ~330 scalar ops per
// circuit in ONE THREAD. 8192 threads total (~85K warp-issues, 65x less).
//
// Derivation (bit p = 9 - qubit q; CNOT chain P is the GF(2) suffix-XOR M):
//   psi = P R2 P R1 |0>,   out = sum_p <psi| Z_p |psi>
//   <Z_p> = <chi| R2^T (P^T Z_p P) R2 |chi>,  chi = P R1|0>
//   P^T Z_p P = Z_p Z_{p+1} ... Z_9          (suffix Z-string)
//   R2^T Z_m R2 = cos(t2) Z_m - sin(t2) X_m  (per site, FULL angle t2)
//   chi_j = prod_b f_b(j_b ^ j_{b+1}), j_10=0, f_b = (cos(t1/2), sin(t1/2))
//     -- an MPS of bond dim 2 (M^-1 is adjacent-XOR).
// Contraction: symmetric 2x2 environment S (s00,s01,s11) swept from bit 9
// down to 0: M = F_p S F_p (F_p = [[c,s],[s,c]]), then S <- g_p . M with
// g = (gamma, -sigma, -gamma). Left I-environment d_p (2 diag components,
// d_{p+1}[u] = d_p[0] f_p(u)^2 + d_p[1] f_p(u^1)^2). Each term:
//   E_{p+1} = d_p[0] M00 + d_p[1] M11   (read during the sweep, ~free)
//   E_0     = s00 + 2 s01 + s11         (final full sum)
// Verified analytically on 4 independent angle configurations.

__global__ __launch_bounds__(64)
void qnn_kernel(const float* __restrict__ x,      // [128, 10]
                const float* __restrict__ w,      // [64, 10, 2]
                float* __restrict__ out)          // [64, 128] flat
{
    const int t  = blockIdx.x * 64 + threadIdx.x;   // 0..8191, one circuit
    const int of = t >> 7;          // out_feature (warp-uniform)
    const int nb = t & 127;         // batch row

    // --- Vectorized loads: x row = 5 x float2 (8B-aligned), w row = 5 x float4.
    float xv[10], wv[20];
    {
        const float2* xp = (const float2*)(x + nb * 10);
#pragma unroll
        for (int i = 0; i < 5; i++) {
            const float2 v = xp[i];
            xv[2*i] = v.x; xv[2*i+1] = v.y;
        }
        const float4* wp = (const float4*)(w + of * 20);
#pragma unroll
        for (int i = 0; i < 5; i++) {
            const float4 v = wp[i];
            wv[4*i] = v.x; wv[4*i+1] = v.y; wv[4*i+2] = v.z; wv[4*i+3] = v.w;
        }
    }

    // --- Per-bit angle data. Bit p <-> qubit q = 9-p.
    //     f_p = (cos(t1/2), sin(t1/2));  gamma/sigma = cos(t2), sin(t2) (FULL).
    float fc[10], fs[10], ga[10], sg[10];
#pragma unroll
    for (int q = 0; q < 10; q++) {
        const int p = 9 - q;
        const float t1 = xv[q] + wv[2*q];
        const float t2 = wv[2*q + 1];
        __sincosf(0.5f * t1, &fs[p], &fc[p]);
        __sincosf(t2,        &sg[p], &ga[p]);
    }

    // --- Left diagonal environments d_p (p = 0..8), built bottom-up.
    float d0[9], d1[9];
    d0[0] = 1.0f; d1[0] = 1.0f;
#pragma unroll
    for (int p = 0; p < 8; p++) {
        const float a = fc[p] * fc[p];
        const float b = fs[p] * fs[p];
        d0[p+1] = fmaf(d0[p], a, d1[p] * b);
        d1[p+1] = fmaf(d0[p], b, d1[p] * a);
    }

    // --- Top boundary step (p = 9): S_10 = e_(0,0) -> M = outer(f9, f9).
    float s00, s01, s11;
    {
        const float c = fc[9], s = fs[9];
        s00 =  ga[9] * (c * c);
        s01 = -sg[9] * (c * s);
        s11 = -ga[9] * (s * s);
    }

    // --- Sweep p = 8..0: M = F_p S F_p; E_{p+1} = d_p . diag(M); S = g_p . M.
    float outv = 0.0f;
#pragma unroll
    for (int p = 8; p >= 0; p--) {
        const float c = fc[p], s = fs[p];
        const float t0  = fmaf(c, s00, s * s01);
        const float t1v = fmaf(c, s01, s * s11);
        const float t2v = fmaf(s, s00, c * s01);
        const float t3v = fmaf(s, s01, c * s11);
        const float M00 = fmaf(c, t0,  s * t1v);
        const float M01 = fmaf(s, t0,  c * t1v);
        const float M11 = fmaf(s, t2v, c * t3v);
        outv += fmaf(d0[p], M00, d1[p] * M11);     // E_{p+1}
        s00 =  ga[p] * M00;
        s01 = -sg[p] * M01;
        s11 = -ga[p] * M11;
    }

    // --- E_0 = full contraction of S_0 (off-diagonal counted twice).
    outv += s00 + 2.0f * s01 + s11;

    out[t] = outv;   // out[of * 128 + nb]
}

extern "C" void kernel_launch(void* const* d_in, const int* in_sizes, int n_in,
                              void* d_out, int out_size)
{
    const float* x = (const float*)d_in[0];   // (128, 10) fp32
    const float* w = (const float*)d_in[1];   // (64, 10, 2) fp32
    float* out = (float*)d_out;               // 8192 fp32

    // One THREAD per circuit: 8192 threads, 64/block -> 128 blocks spread
    // across SMs. Latency-bound (~600-900 cy critical path), not throughput.
    qnn_kernel<<<128, 64>>>(x, w, out);
}

// round 13
// speedup vs baseline: 1.5414x; 1.1878x over previous
#include <cuda_runtime.h>

// QNN_72988674228630: 10-qubit, 2-layer RY+CNOT circuit, 8192 circuits.
//
// R13: same bond-2 MPS transfer-matrix contraction as R12 (~330 scalar ops,
// ONE thread per circuit), but with the register budget uncapped
// (__launch_bounds__(32,1): up to 255 regs) so the ~88-float live set
// (angles, per-bit f/g factors, left environments) is fully register-resident.
// R12's __launch_bounds__(64) let ptxas target 48 regs and spill the unrolled
// arrays to local memory — dozens of serialized LDL/STL on a 2-warp/SM kernel.
// Grid reshaped to 256 blocks x 32 threads so all 148 SMs receive work.
//
// Derivation (bit p = 9 - qubit q; CNOT chain P = GF(2) suffix-XOR M):
//   psi = P R2 P R1 |0>,  out = sum_p <psi| Z_p |psi>
//   P^T Z_p P = Z_p Z_{p+1} ... Z_9             (suffix Z-string)
//   R2^T Z_m R2 = cos(t2) Z_m - sin(t2) X_m     (per site, FULL angle)
//   chi_j = prod_b f_b(j_b ^ j_{b+1})           (bond-2 MPS, f = (cos,sin) of t1/2)
// Contraction: symmetric 2x2 environment S swept p=9..0 with M = F_p S F_p,
// S <- (ga, -sg, -ga) . M; left diagonal environment d_p built p=0..8;
// E_{p+1} = d_p . diag(M) read during the sweep; E_0 = full sum of S_0.

__global__ __launch_bounds__(32, 1)
void qnn_kernel(const float* __restrict__ x,      // [128, 10]
                const float* __restrict__ w,      // [64, 10, 2]
                float* __restrict__ out)          // [64, 128] flat
{
    const int t  = blockIdx.x * 32 + threadIdx.x;   // 0..8191, one circuit
    const int of = t >> 7;          // out_feature (warp-uniform -> broadcast loads)
    const int nb = t & 127;         // batch row (consecutive across lanes)

    // --- Loads: x row = 5 x float2 (8B aligned), w row = 5 x float4 (uniform).
    float xv[10], wv[20];
    {
        const float2* xp = (const float2*)(x + nb * 10);
#pragma unroll
        for (int i = 0; i < 5; i++) {
            const float2 v = xp[i];
            xv[2*i] = v.x; xv[2*i+1] = v.y;
        }
        const float4* wp = (const float4*)(w + of * 20);
#pragma unroll
        for (int i = 0; i < 5; i++) {
            const float4 v = wp[i];
            wv[4*i] = v.x; wv[4*i+1] = v.y; wv[4*i+2] = v.z; wv[4*i+3] = v.w;
        }
    }

    // --- Per-bit angle data. Bit p <-> qubit q = 9-p.
    float fc[10], fs[10], ga[10], sg[10];
#pragma unroll
    for (int q = 0; q < 10; q++) {
        const int p = 9 - q;
        __sincosf(0.5f * (xv[q] + wv[2*q]), &fs[p], &fc[p]);
        __sincosf(wv[2*q + 1],              &sg[p], &ga[p]);
    }

    // --- Left diagonal environments d_p (p = 0..8), bottom-up.
    float d0[9], d1[9];
    d0[0] = 1.0f; d1[0] = 1.0f;
#pragma unroll
    for (int p = 0; p < 8; p++) {
        const float a = fc[p] * fc[p];
        const float b = fs[p] * fs[p];
        d0[p+1] = fmaf(d0[p], a, d1[p] * b);
        d1[p+1] = fmaf(d0[p], b, d1[p] * a);
    }

    // --- Top boundary (p = 9): S = (ga,-sg,-ga) . outer(f9, f9).
    float s00, s01, s11;
    {
        const float c = fc[9], s = fs[9];
        s00 =  ga[9] * (c * c);
        s01 = -sg[9] * (c * s);
        s11 = -ga[9] * (s * s);
    }

    // --- Sweep p = 8..0. Two accumulator chains to shorten the tail.
    float acc0 = 0.0f, acc1 = 0.0f;
#pragma unroll
    for (int p = 8; p >= 0; p--) {
        const float c = fc[p], s = fs[p];
        const float t0  = fmaf(c, s00, s * s01);
        const float t1v = fmaf(c, s01, s * s11);
        const float t2v = fmaf(s, s00, c * s01);
        const float t3v = fmaf(s, s01, c * s11);
        const float M00 = fmaf(c, t0,  s * t1v);
        const float M01 = fmaf(s, t0,  c * t1v);
        const float M11 = fmaf(s, t2v, c * t3v);
        if (p & 1) acc1 = fmaf(d0[p], M00, fmaf(d1[p], M11, acc1));
        else       acc0 = fmaf(d0[p], M00, fmaf(d1[p], M11, acc0));
        s00 =  ga[p] * M00;
        s01 = -sg[p] * M01;
        s11 = -ga[p] * M11;
    }

    // --- E_0 = full contraction of S_0 (off-diagonal twice).
    out[t] = acc0 + acc1 + s00 + 2.0f * s01 + s11;
}

extern "C" void kernel_launch(void* const* d_in, const int* in_sizes, int n_in,
                              void* d_out, int out_size)
{
    const float* x = (const float*)d_in[0];   // (128, 10) fp32
    const float* w = (const float*)d_in[1];   // (64, 10, 2) fp32
    float* out = (float*)d_out;               // 8192 fp32

    // One thread per circuit; 256 blocks x 32 threads covers all 148 SMs.
    qnn_kernel<<<256, 32>>>(x, w, out);
}